// round 12
// baseline (speedup 1.0000x reference)
#include <cuda_runtime.h>
#include <cuda_fp16.h>
#include <cuda_fp8.h>

// Inter_domain_loss as ONE persistent kernel, v6: atomicAdd accumulators
// replace the strided gather-reduce phases (P1/P3 of v5) entirely.
// 128 CTAs x 512 threads; CTA holds 32 rows fp8(G+eps) in SMEM.
// P0: cp.async G pipeline (warps 0-7) || deep-LDG mean stream (warps 8-15),
// partials land in global accumulators via REDG. Consumers invert locally.
// 2 Sinkhorn iterations (fp8, rel_err ~2.6e-6 validated R6-R11).

#define NN      4096
#define BB      2048
#define EPSV    1e-5f
#define NCTA    128
#define RPC     32
#define MRPC    16
#define THREADS 512
#define SDEPTH  4
#define INV_BB  (1.0f / 2048.0f)

// smem layout
#define SM_G8    0                    // 131072
#define SM_STAGE 131072               // 65536 (P0 staging ring)
#define SM_RED   196608               // 2048: wpart[16*32] / redT+redW
#define SM_U     198656               // 128: ush[32]
#define SM_MT    198784               // 128: mtr[32]
#define SM_TOT   198912

// Global accumulators (zeroed in-kernel before use)
__device__ float d_colsum1[NN];
__device__ float d_colsum2[NN];
__device__ float d_meanS[NN];
__device__ float d_meanT[NN];
__device__ float d_ctapart[NCTA];
__device__ unsigned d_barcnt = 0;
__device__ unsigned d_bargen = 0;

#define CP_ASYNC16(dst, src) \
    asm volatile("cp.async.cg.shared.global [%0], [%1], 16;\n" :: "r"(dst), "l"(src))
#define CP_COMMIT() asm volatile("cp.async.commit_group;\n" ::: "memory")
#define CP_WAIT3()  asm volatile("cp.async.wait_group 3;\n" ::: "memory")
#define CP_WAIT0()  asm volatile("cp.async.wait_group 0;\n" ::: "memory")

// ---------------------------------------------------------------------------
__device__ __forceinline__ void grid_barrier() {
    __syncthreads();
    if (threadIdx.x == 0) {
        __threadfence();
        unsigned gen = atomicAdd(&d_bargen, 0u);
        unsigned old = atomicAdd(&d_barcnt, 1u);
        if (old == NCTA - 1) {
            atomicExch(&d_barcnt, 0u);
            atomicAdd(&d_bargen, 1u);
        } else {
            while (atomicAdd(&d_bargen, 0u) == gen) __nanosleep(32);
        }
    }
    __syncthreads();
}

__device__ __forceinline__ void fp8x4_to_f32(unsigned raw, float* f) {
    __half2_raw h0 = __nv_cvt_fp8x2_to_halfraw2((__nv_fp8x2_storage_t)(raw & 0xFFFFu), __NV_E4M3);
    __half2_raw h1 = __nv_cvt_fp8x2_to_halfraw2((__nv_fp8x2_storage_t)(raw >> 16), __NV_E4M3);
    float2 a = __half22float2(*reinterpret_cast<__half2*>(&h0));
    float2 b = __half22float2(*reinterpret_cast<__half2*>(&h1));
    f[0] = a.x; f[1] = a.y; f[2] = b.x; f[3] = b.y;
}

__device__ __forceinline__ float4 ldcs4(const float* p) {
    return __ldcs(reinterpret_cast<const float4*>(p));
}

// Butterfly array-reduce: 32 per-lane values -> lane l returns total of row l.
__device__ __forceinline__ float bfly_reduce32(const float* a, int l) {
    float b[16];
#pragma unroll
    for (int r = 0; r < 16; ++r) {
        bool hi = (l & 16);
        float send = hi ? a[r] : a[r + 16];
        float keep = hi ? a[r + 16] : a[r];
        b[r] = keep + __shfl_xor_sync(0xffffffffu, send, 16);
    }
    float c[8];
#pragma unroll
    for (int r = 0; r < 8; ++r) {
        bool hi = (l & 8);
        float send = hi ? b[r] : b[r + 8];
        float keep = hi ? b[r + 8] : b[r];
        c[r] = keep + __shfl_xor_sync(0xffffffffu, send, 8);
    }
    float d[4];
#pragma unroll
    for (int r = 0; r < 4; ++r) {
        bool hi = (l & 4);
        float send = hi ? c[r] : c[r + 4];
        float keep = hi ? c[r + 4] : c[r];
        d[r] = keep + __shfl_xor_sync(0xffffffffu, send, 4);
    }
    float e[2];
#pragma unroll
    for (int r = 0; r < 2; ++r) {
        bool hi = (l & 2);
        float send = hi ? d[r] : d[r + 2];
        float keep = hi ? d[r + 2] : d[r];
        e[r] = keep + __shfl_xor_sync(0xffffffffu, send, 2);
    }
    bool hi = (l & 1);
    float send = hi ? e[0] : e[1];
    float keep = hi ? e[1] : e[0];
    return keep + __shfl_xor_sync(0xffffffffu, send, 1);
}

// 16 per-lane values -> lanes l and l+16 return total of row (l & 15).
__device__ __forceinline__ float bfly_reduce16(const float* a, int l) {
    float b[16];
#pragma unroll
    for (int r = 0; r < 16; ++r) b[r] = a[r] + __shfl_xor_sync(0xffffffffu, a[r], 16);
    float c[8];
#pragma unroll
    for (int r = 0; r < 8; ++r) {
        bool hi = (l & 8);
        float send = hi ? b[r] : b[r + 8];
        float keep = hi ? b[r + 8] : b[r];
        c[r] = keep + __shfl_xor_sync(0xffffffffu, send, 8);
    }
    float d[4];
#pragma unroll
    for (int r = 0; r < 4; ++r) {
        bool hi = (l & 4);
        float send = hi ? c[r] : c[r + 4];
        float keep = hi ? c[r + 4] : c[r];
        d[r] = keep + __shfl_xor_sync(0xffffffffu, send, 4);
    }
    float e[2];
#pragma unroll
    for (int r = 0; r < 2; ++r) {
        bool hi = (l & 2);
        float send = hi ? d[r] : d[r + 2];
        float keep = hi ? d[r + 2] : d[r];
        e[r] = keep + __shfl_xor_sync(0xffffffffu, send, 2);
    }
    bool hi = (l & 1);
    float send = hi ? e[0] : e[1];
    float keep = hi ? e[1] : e[0];
    return keep + __shfl_xor_sync(0xffffffffu, send, 1);
}

// ---------------------------------------------------------------------------
__global__ __launch_bounds__(THREADS, 1)
void k_fused(const float* __restrict__ src, const float* __restrict__ trg,
             const float* __restrict__ G, float* __restrict__ out) {
    extern __shared__ unsigned char smem[];
    unsigned char* g8  = smem + SM_G8;
    float* wpart = reinterpret_cast<float*>(smem + SM_RED);        // [16][32]
    float* redT  = reinterpret_cast<float*>(smem + SM_RED);        // [16][16]
    float* redW  = reinterpret_cast<float*>(smem + SM_RED + 1024); // [16][16]
    float* ush   = reinterpret_cast<float*>(smem + SM_U);
    float* mtr   = reinterpret_cast<float*>(smem + SM_MT);

    const int b  = blockIdx.x;
    const int t  = threadIdx.x;
    const int r0 = b * RPC;
    const int w  = t >> 5, l = t & 31;

    unsigned stage_base;
    {
        const void* sp = smem + SM_STAGE;
        asm("{ .reg .u64 tmp; cvta.to.shared.u64 tmp, %1; cvt.u32.u64 %0, tmp; }"
            : "=r"(stage_base) : "l"(sp));
    }

    // ===== Z: zero this CTA's 32-column slice of all accumulators =====
    if (t < 128) {
        int which = t >> 5;
        int col = b * 32 + (t & 31);
        if      (which == 0) d_colsum1[col] = 0.f;
        else if (which == 1) d_colsum2[col] = 0.f;
        else if (which == 2) d_meanS[col]   = 0.f;
        else                 d_meanT[col]   = 0.f;
    }
    grid_barrier();   // reached during launch skew; guarantees zeroing chip-wide

    // ===== P0 (warp-specialized): cp.async G pipeline || deep-LDG means =====
    if (t < 256) {
        const int c = t * 16;
        float acc[16];
#pragma unroll
        for (int k = 0; k < 16; ++k) acc[k] = 0.f;

#pragma unroll
        for (int d = 0; d < SDEPTH - 1; ++d) {
            const float* gp = G + (size_t)(r0 + d) * NN + c;
            unsigned sdst = stage_base + (unsigned)((d * NN + c) * 4);
#pragma unroll
            for (int q = 0; q < 4; ++q) CP_ASYNC16(sdst + 16u * q, gp + 4 * q);
            CP_COMMIT();
        }

        for (int r = 0; r < RPC; ++r) {
            if (r + SDEPTH - 1 < RPC) {
                const float* gp = G + (size_t)(r0 + r + SDEPTH - 1) * NN + c;
                unsigned sdst = stage_base + (unsigned)((((r + SDEPTH - 1) & (SDEPTH - 1)) * NN + c) * 4);
#pragma unroll
                for (int q = 0; q < 4; ++q) CP_ASYNC16(sdst + 16u * q, gp + 4 * q);
            }
            CP_COMMIT();
            CP_WAIT3();

            const float* st = reinterpret_cast<const float*>(smem + SM_STAGE)
                              + (r & (SDEPTH - 1)) * NN + c;
            float4 a0 = *reinterpret_cast<const float4*>(st);
            float4 a1 = *reinterpret_cast<const float4*>(st + 4);
            float4 a2 = *reinterpret_cast<const float4*>(st + 8);
            float4 a3 = *reinterpret_cast<const float4*>(st + 12);
            float e[16] = {a0.x + EPSV, a0.y + EPSV, a0.z + EPSV, a0.w + EPSV,
                           a1.x + EPSV, a1.y + EPSV, a1.z + EPSV, a1.w + EPSV,
                           a2.x + EPSV, a2.y + EPSV, a2.z + EPSV, a2.w + EPSV,
                           a3.x + EPSV, a3.y + EPSV, a3.z + EPSV, a3.w + EPSV};
            uint4 packed;
            __nv_fp8x2_storage_t* p = reinterpret_cast<__nv_fp8x2_storage_t*>(&packed);
#pragma unroll
            for (int k = 0; k < 8; ++k) {
                p[k] = __nv_cvt_float2_to_fp8x2(make_float2(e[2 * k], e[2 * k + 1]),
                                                __NV_SATFINITE, __NV_E4M3);
                acc[2 * k]     += e[2 * k];
                acc[2 * k + 1] += e[2 * k + 1];
            }
            *reinterpret_cast<uint4*>(g8 + r * NN + c) = packed;
        }
        CP_WAIT0();
#pragma unroll
        for (int k = 0; k < 16; ++k) atomicAdd(d_colsum1 + c + k, acc[k]);
    } else {
        const int c = (t - 256) * 16;
        const int m0 = b * MRPC;
        float accS[16], accT[16];
#pragma unroll
        for (int k = 0; k < 16; ++k) { accS[k] = 0.f; accT[k] = 0.f; }

        const float* sp0 = src + (size_t)m0 * NN + c;
        const float* tp0 = trg + (size_t)m0 * NN + c;
        float4 s0 = ldcs4(sp0), s1 = ldcs4(sp0 + 4), s2 = ldcs4(sp0 + 8), s3 = ldcs4(sp0 + 12);
        float4 t0 = ldcs4(tp0), t1 = ldcs4(tp0 + 4), t2 = ldcs4(tp0 + 8), t3 = ldcs4(tp0 + 12);
        for (int r = 0; r < MRPC; ++r) {
            float4 cs0 = s0, cs1 = s1, cs2 = s2, cs3 = s3;
            float4 ct0 = t0, ct1 = t1, ct2 = t2, ct3 = t3;
            if (r + 1 < MRPC) {
                const float* sp = src + (size_t)(m0 + r + 1) * NN + c;
                const float* tp = trg + (size_t)(m0 + r + 1) * NN + c;
                s0 = ldcs4(sp); s1 = ldcs4(sp + 4); s2 = ldcs4(sp + 8); s3 = ldcs4(sp + 12);
                t0 = ldcs4(tp); t1 = ldcs4(tp + 4); t2 = ldcs4(tp + 8); t3 = ldcs4(tp + 12);
            }
            accS[0] += cs0.x; accS[1] += cs0.y; accS[2]  += cs0.z; accS[3]  += cs0.w;
            accS[4] += cs1.x; accS[5] += cs1.y; accS[6]  += cs1.z; accS[7]  += cs1.w;
            accS[8] += cs2.x; accS[9] += cs2.y; accS[10] += cs2.z; accS[11] += cs2.w;
            accS[12]+= cs3.x; accS[13]+= cs3.y; accS[14] += cs3.z; accS[15] += cs3.w;
            accT[0] += ct0.x; accT[1] += ct0.y; accT[2]  += ct0.z; accT[3]  += ct0.w;
            accT[4] += ct1.x; accT[5] += ct1.y; accT[6]  += ct1.z; accT[7]  += ct1.w;
            accT[8] += ct2.x; accT[9] += ct2.y; accT[10] += ct2.z; accT[11] += ct2.w;
            accT[12]+= ct3.x; accT[13]+= ct3.y; accT[14] += ct3.z; accT[15] += ct3.w;
        }
#pragma unroll
        for (int k = 0; k < 16; ++k) {
            atomicAdd(d_meanS + c + k, accS[k]);
            atomicAdd(d_meanT + c + k, accT[k]);
        }
    }
    grid_barrier();

    // ===== P2: local v1 = 1/colsum1; rowdots -> u; colsum(u) atomics =====
    {
        const int c = t * 8;
        float cs[8];
        *reinterpret_cast<float4*>(cs)     = __ldcg(reinterpret_cast<const float4*>(d_colsum1 + c));
        *reinterpret_cast<float4*>(cs + 4) = __ldcg(reinterpret_cast<const float4*>(d_colsum1 + c + 4));
        float vreg[8];
#pragma unroll
        for (int k = 0; k < 8; ++k) vreg[k] = __fdividef(1.0f, cs[k]);

        float acc[32];
#pragma unroll 8
        for (int r = 0; r < RPC; ++r) {
            uint2 raw = *reinterpret_cast<const uint2*>(g8 + r * NN + c);
            float f[8];
            fp8x4_to_f32(raw.x, f);
            fp8x4_to_f32(raw.y, f + 4);
            acc[r] = f[0] * vreg[0] + f[1] * vreg[1] + f[2] * vreg[2] + f[3] * vreg[3]
                   + f[4] * vreg[4] + f[5] * vreg[5] + f[6] * vreg[6] + f[7] * vreg[7];
        }
        float rowdot = bfly_reduce32(acc, l);
        wpart[w * 32 + l] = rowdot;
        __syncthreads();
        if (t < 32) {
            float s = 0.f;
#pragma unroll
            for (int w2 = 0; w2 < 16; ++w2) s += wpart[w2 * 32 + t];
            ush[t] = __fdividef(1.0f, s);
        }
        __syncthreads();

        float ca[8] = {0.f, 0.f, 0.f, 0.f, 0.f, 0.f, 0.f, 0.f};
#pragma unroll 8
        for (int r = 0; r < RPC; ++r) {
            float u = ush[r];
            uint2 raw = *reinterpret_cast<const uint2*>(g8 + r * NN + c);
            float f[8];
            fp8x4_to_f32(raw.x, f);
            fp8x4_to_f32(raw.y, f + 4);
#pragma unroll
            for (int k = 0; k < 8; ++k) ca[k] += u * f[k];
        }
#pragma unroll
        for (int k = 0; k < 8; ++k) atomicAdd(d_colsum2 + c + k, ca[k]);
    }
    grid_barrier();

    // ===== P4: local v2 = 1/colsum2; exact row-normalize + loss =====
    {
        const int c = t * 8;
        float cs[8], msreg[8], vreg[8];
        *reinterpret_cast<float4*>(cs)        = __ldcg(reinterpret_cast<const float4*>(d_colsum2 + c));
        *reinterpret_cast<float4*>(cs + 4)    = __ldcg(reinterpret_cast<const float4*>(d_colsum2 + c + 4));
        *reinterpret_cast<float4*>(msreg)     = __ldcg(reinterpret_cast<const float4*>(d_meanS + c));
        *reinterpret_cast<float4*>(msreg + 4) = __ldcg(reinterpret_cast<const float4*>(d_meanS + c + 4));
#pragma unroll
        for (int k = 0; k < 8; ++k) {
            vreg[k]  = __fdividef(1.0f, cs[k]);
            msreg[k] *= INV_BB;
        }
        if (t < 32) mtr[t] = __ldcg(d_meanT + r0 + t) * INV_BB;
        __syncthreads();

        float loss_acc = 0.f;
#pragma unroll
        for (int ch = 0; ch < 2; ++ch) {
            float att[16], aww[16];
#pragma unroll 4
            for (int r16 = 0; r16 < 16; ++r16) {
                int r = ch * 16 + r16;
                uint2 raw = *reinterpret_cast<const uint2*>(g8 + r * NN + c);
                float f[8];
                fp8x4_to_f32(raw.x, f);
                fp8x4_to_f32(raw.y, f + 4);
                float mt = mtr[r];
                float at = 0.f, aw = 0.f;
#pragma unroll
                for (int k = 0; k < 8; ++k) {
                    float gv = f[k] * vreg[k];
                    at += gv;
                    aw += fabsf(mt - msreg[k]) * gv;
                }
                att[r16] = at;
                aww[r16] = aw;
            }
            float atf = bfly_reduce16(att, l);
            float awf = bfly_reduce16(aww, l);
            if (l < 16) {
                redT[w * 16 + l] = atf;
                redW[w * 16 + l] = awf;
            }
            __syncthreads();
            if (t < 16) {
                float at = 0.f, aw = 0.f;
#pragma unroll
                for (int w2 = 0; w2 < 16; ++w2) {
                    at += redT[w2 * 16 + t];
                    aw += redW[w2 * 16 + t];
                }
                loss_acc += aw / at;
            }
            __syncthreads();
        }
        if (t < 16) {
#pragma unroll
            for (int off = 8; off; off >>= 1)
                loss_acc += __shfl_down_sync(0x0000ffffu, loss_acc, off, 16);
            if (t == 0) d_ctapart[b] = loss_acc;
        }
    }
    grid_barrier();

    // ===== P5: CTA 0 reduces 128 partials =====
    if (b == 0 && t < 32) {
        float s = 0.f;
#pragma unroll
        for (int k = 0; k < NCTA / 32; ++k) s += __ldcg(d_ctapart + t + 32 * k);
#pragma unroll
        for (int off = 16; off; off >>= 1) s += __shfl_down_sync(0xffffffffu, s, off);
        if (t == 0) out[0] = s;
    }
}

// ---------------------------------------------------------------------------
extern "C" void kernel_launch(void* const* d_in, const int* in_sizes, int n_in,
                              void* d_out, int out_size) {
    (void)in_sizes; (void)n_in; (void)out_size;
    const float* src = (const float*)d_in[0];
    const float* trg = (const float*)d_in[1];
    const float* G   = (const float*)d_in[2];
    float* out = (float*)d_out;

    cudaFuncSetAttribute(k_fused, cudaFuncAttributeMaxDynamicSharedMemorySize, SM_TOT);
    k_fused<<<NCTA, THREADS, SM_TOT>>>(src, trg, G, out);
}